// round 3
// baseline (speedup 1.0000x reference)
#include <cuda_runtime.h>

#define Nn 100000
#define Ee 1000000
#define NB ((size_t)Nn * 64 * sizeof(float))
#define GB2 ((Nn + 127) / 128)     /* 782 gemm blocks  */
#define SB  (Ee / 64)              /* 15625 scatter blocks (64 edges each) */

// Scratch (device globals — no runtime allocation allowed)
__device__ float g_H[2][(size_t)Nn * 64];   // encoder hidden
__device__ float g_Yb[2][(size_t)Nn * 64];
__device__ float g_Xb[2][(size_t)Nn * 64];
__device__ float g_Ab[6][(size_t)Nn * 64];  // agg: [g*3 + layer]
__device__ float g_D[2][Nn];
__device__ float g_Wp[2][64 * 64];          // w2 @ W0
__device__ float g_bp[2][64];               // b2 @ W0

// ---------------------------------------------------------------------------
// Tiny precompute: Wp[g] = w2 @ cw[0];  bp[g] = b2 @ cw[0]
// ---------------------------------------------------------------------------
__global__ void prep_k(const float* __restrict__ w2a, const float* __restrict__ b2a,
                       const float* __restrict__ cwa,
                       const float* __restrict__ w2b, const float* __restrict__ b2b,
                       const float* __restrict__ cwb,
                       float* __restrict__ wp, float* __restrict__ bp) {
    int g = blockIdx.x;
    const float* w2 = g ? w2b : w2a;
    const float* b2 = g ? b2b : b2a;
    const float* cw = g ? cwb : cwa;
    __shared__ float A[4096], B[4096];
    int tid = threadIdx.x;
#pragma unroll
    for (int t = 0; t < 16; t++) {
        A[tid + t * 256] = w2[tid + t * 256];
        B[tid + t * 256] = cw[tid + t * 256];
    }
    __syncthreads();
    float* WP = wp + g * 4096;
#pragma unroll
    for (int t = 0; t < 16; t++) {
        int idx = tid + t * 256;
        int i = idx >> 6, j = idx & 63;
        float s = 0.f;
#pragma unroll 16
        for (int k = 0; k < 64; k++) s = fmaf(A[i * 64 + k], B[k * 64 + j], s);
        WP[idx] = s;
    }
    if (tid < 64) {
        float s = 0.f;
        for (int k = 0; k < 64; k++) s = fmaf(b2[k], B[k * 64 + tid], s);
        bp[g * 64 + tid] = s;
    }
}

// ---------------------------------------------------------------------------
// Degree: deg[dst] += 1 per edge; then dinv = rsqrt(deg + 1)  (self-loop)
// ---------------------------------------------------------------------------
__global__ void deg_count_k(const int* __restrict__ f, const int* __restrict__ s,
                            float* __restrict__ d0, float* __restrict__ d1) {
    int e = blockIdx.x * blockDim.x + threadIdx.x;
    if (e < Ee) {
        atomicAdd(d0 + __ldg(f + Ee + e), 1.f);
        atomicAdd(d1 + __ldg(s + Ee + e), 1.f);
    }
}

__global__ void dinv_k(float* __restrict__ d0, float* __restrict__ d1) {
    int i = blockIdx.x * blockDim.x + threadIdx.x;
    if (i < Nn) {
        d0[i] = rsqrtf(d0[i] + 1.f);
        d1[i] = rsqrtf(d1[i] + 1.f);
    }
}

// ---------------------------------------------------------------------------
// Encoder hidden (both graphs): h[g][r,j] = relu(b1[j] + sum_{k<4} x[r,k]*w1[k,j])
// ---------------------------------------------------------------------------
__global__ void enc2_k(const float* __restrict__ x0, const float* __restrict__ w10,
                       const float* __restrict__ b10,
                       const float* __restrict__ x1, const float* __restrict__ w11,
                       const float* __restrict__ b11, float* __restrict__ h) {
    int g = blockIdx.y;
    const float* x = g ? x1 : x0;
    const float* w1 = g ? w11 : w10;
    const float* b1 = g ? b11 : b10;
    int t = blockIdx.x * blockDim.x + threadIdx.x;
    if (t >= Nn * 64) return;
    int r = t >> 6, j = t & 63;
    float4 xv = *(const float4*)(x + (size_t)r * 4);
    float v = __ldg(b1 + j)
            + xv.x * __ldg(w1 + j)       + xv.y * __ldg(w1 + 64 + j)
            + xv.z * __ldg(w1 + 128 + j) + xv.w * __ldg(w1 + 192 + j);
    h[(size_t)g * Nn * 64 + t] = fmaxf(v, 0.f);
}

// ---------------------------------------------------------------------------
// Combo kernel: blocks [0, nG) do a 128x64 GEMM tile; blocks [nG, nG+SB) do
// edge scatter (64 edges/block, 16 lanes/edge, 4 edges/group, float4 red ops).
//
// GEMM input modes:
//   gcnIn=0: v = inA[r,c]
//   gcnIn=1: v = relu(dinv[r]*(inAgg[r,c]+inA[r,c]) + inBias[c])
// GEMM output: out[r,c] (+= if accum) (acc + outBias[c]) * (outDinv ? dinv[r] : 1)
// Scatter: sagg[dst,:] += sy[src,:]
// ---------------------------------------------------------------------------
__global__ __launch_bounds__(256) void combo_k(
    int nG,
    const float* __restrict__ inA, const float* __restrict__ inAgg,
    const float* __restrict__ inDinv, const float* __restrict__ inBias,
    const float* __restrict__ W, const float* __restrict__ outBias,
    const float* __restrict__ outDinv, float* __restrict__ out,
    int gcnIn, int accum,
    const float* __restrict__ sy, const int* __restrict__ sei,
    float* __restrict__ sagg) {

    if ((int)blockIdx.x >= nG) {
        // ------------------ scatter path ------------------
        int b = blockIdx.x - nG;
        int t = threadIdx.x;
        int e0 = (b * 16 + (t >> 4)) * 4;
        int j = (t & 15) * 4;
        const int* srcp = sei;
        const int* dstp = sei + Ee;
        int s0 = __ldg(srcp + e0),     s1 = __ldg(srcp + e0 + 1);
        int s2 = __ldg(srcp + e0 + 2), s3 = __ldg(srcp + e0 + 3);
        int d0 = __ldg(dstp + e0),     d1 = __ldg(dstp + e0 + 1);
        int d2 = __ldg(dstp + e0 + 2), d3 = __ldg(dstp + e0 + 3);
        float4 v0 = *(const float4*)(sy + (size_t)s0 * 64 + j);
        float4 v1 = *(const float4*)(sy + (size_t)s1 * 64 + j);
        float4 v2 = *(const float4*)(sy + (size_t)s2 * 64 + j);
        float4 v3 = *(const float4*)(sy + (size_t)s3 * 64 + j);
        atomicAdd((float4*)(sagg + (size_t)d0 * 64 + j), v0);
        atomicAdd((float4*)(sagg + (size_t)d1 * 64 + j), v1);
        atomicAdd((float4*)(sagg + (size_t)d2 * 64 + j), v2);
        atomicAdd((float4*)(sagg + (size_t)d3 * 64 + j), v3);
        return;
    }

    // ------------------ GEMM path ------------------
    __shared__ float Xs[128 * 64];   // 32 KB
    __shared__ float Ws[64 * 64];    // 16 KB

    int tid = threadIdx.x;
    int row0 = blockIdx.x * 128;

    const float4* W4 = (const float4*)W;
#pragma unroll
    for (int t = 0; t < 4; t++) ((float4*)Ws)[tid + t * 256] = __ldg(W4 + tid + t * 256);

#pragma unroll
    for (int t = 0; t < 8; t++) {
        int lin = tid + t * 256;        // float4 index; row = lin>>4, col4 = lin&15
        int r = lin >> 4;
        float4 v = make_float4(0.f, 0.f, 0.f, 0.f);
        if (row0 + r < Nn) {
            size_t idx = (size_t)(row0 + r) * 16 + (lin & 15);
            if (!gcnIn) {
                v = ((const float4*)inA)[idx];
            } else {
                float4 a = ((const float4*)inA)[idx];
                float4 g = ((const float4*)inAgg)[idx];
                float dv = inDinv[row0 + r];
                float4 b = __ldg((const float4*)inBias + (lin & 15));
                v.x = fmaxf(fmaf(dv, g.x + a.x, b.x), 0.f);
                v.y = fmaxf(fmaf(dv, g.y + a.y, b.y), 0.f);
                v.z = fmaxf(fmaf(dv, g.z + a.z, b.z), 0.f);
                v.w = fmaxf(fmaf(dv, g.w + a.w, b.w), 0.f);
            }
        }
        ((float4*)Xs)[lin] = v;
    }
    __syncthreads();

    int cx = (tid & 15) * 4;
    int ry = (tid >> 4) * 8;
    float acc[8][4];
#pragma unroll
    for (int i = 0; i < 8; i++)
#pragma unroll
        for (int j = 0; j < 4; j++) acc[i][j] = 0.f;

#pragma unroll
    for (int k0 = 0; k0 < 64; k0 += 4) {
        float4 w0 = *(const float4*)(Ws + (k0 + 0) * 64 + cx);
        float4 w1 = *(const float4*)(Ws + (k0 + 1) * 64 + cx);
        float4 w2 = *(const float4*)(Ws + (k0 + 2) * 64 + cx);
        float4 w3 = *(const float4*)(Ws + (k0 + 3) * 64 + cx);
#pragma unroll
        for (int i = 0; i < 8; i++) {
            float4 a = *(const float4*)(Xs + (ry + i) * 64 + k0);
            acc[i][0] = fmaf(a.x, w0.x, fmaf(a.y, w1.x, fmaf(a.z, w2.x, fmaf(a.w, w3.x, acc[i][0]))));
            acc[i][1] = fmaf(a.x, w0.y, fmaf(a.y, w1.y, fmaf(a.z, w2.y, fmaf(a.w, w3.y, acc[i][1]))));
            acc[i][2] = fmaf(a.x, w0.z, fmaf(a.y, w1.z, fmaf(a.z, w2.z, fmaf(a.w, w3.z, acc[i][2]))));
            acc[i][3] = fmaf(a.x, w0.w, fmaf(a.y, w1.w, fmaf(a.z, w2.w, fmaf(a.w, w3.w, acc[i][3]))));
        }
    }

    float4 obv = outBias ? __ldg((const float4*)(outBias + cx))
                         : make_float4(0.f, 0.f, 0.f, 0.f);
#pragma unroll
    for (int i = 0; i < 8; i++) {
        int r = row0 + ry + i;
        if (r < Nn) {
            float sc = outDinv ? outDinv[r] : 1.f;
            float4 o = make_float4((acc[i][0] + obv.x) * sc, (acc[i][1] + obv.y) * sc,
                                   (acc[i][2] + obv.z) * sc, (acc[i][3] + obv.w) * sc);
            float* p = out + (size_t)r * 64 + cx;
            if (accum) {
                float4 pv = *(const float4*)p;
                o.x += pv.x; o.y += pv.y; o.z += pv.z; o.w += pv.w;
            }
            *(float4*)p = o;
        }
    }
}

// ---------------------------------------------------------------------------
// Head: fused = relu(h1) @ fw2 + fb2; feats = fused@ow+ob; types = fused@cw+cb
// ---------------------------------------------------------------------------
__global__ __launch_bounds__(256) void head_k(
    const float* __restrict__ h1, const float* __restrict__ fw2, const float* __restrict__ fb2,
    const float* __restrict__ ow, const float* __restrict__ ob,
    const float* __restrict__ cw, const float* __restrict__ cb,
    float* __restrict__ outF, float* __restrict__ outT) {
    __shared__ float Xs[64 * 64];
    __shared__ float Ws[64 * 64];
    int tid = threadIdx.x;
    int row0 = blockIdx.x * 64;
    size_t base = (size_t)row0 * 64;

#pragma unroll
    for (int t = 0; t < 16; t++) Ws[tid + t * 256] = fw2[tid + t * 256];
#pragma unroll
    for (int t = 0; t < 16; t++) {
        int lin = tid + t * 256;
        int r = lin >> 6;
        Xs[lin] = (row0 + r < Nn) ? fmaxf(h1[base + lin], 0.f) : 0.f;
    }
    __syncthreads();

    int cx = (tid & 15) * 4;
    int ry = (tid >> 4) * 4;
    float acc[4][4];
#pragma unroll
    for (int i = 0; i < 4; i++)
#pragma unroll
        for (int j = 0; j < 4; j++) acc[i][j] = 0.f;

#pragma unroll
    for (int k0 = 0; k0 < 64; k0 += 4) {
        float4 w0 = *(const float4*)(Ws + (k0 + 0) * 64 + cx);
        float4 w1 = *(const float4*)(Ws + (k0 + 1) * 64 + cx);
        float4 w2 = *(const float4*)(Ws + (k0 + 2) * 64 + cx);
        float4 w3 = *(const float4*)(Ws + (k0 + 3) * 64 + cx);
#pragma unroll
        for (int i = 0; i < 4; i++) {
            float4 a = *(const float4*)(Xs + (ry + i) * 64 + k0);
            acc[i][0] = fmaf(a.x, w0.x, fmaf(a.y, w1.x, fmaf(a.z, w2.x, fmaf(a.w, w3.x, acc[i][0]))));
            acc[i][1] = fmaf(a.x, w0.y, fmaf(a.y, w1.y, fmaf(a.z, w2.y, fmaf(a.w, w3.y, acc[i][1]))));
            acc[i][2] = fmaf(a.x, w0.z, fmaf(a.y, w1.z, fmaf(a.z, w2.z, fmaf(a.w, w3.z, acc[i][2]))));
            acc[i][3] = fmaf(a.x, w0.w, fmaf(a.y, w1.w, fmaf(a.z, w2.w, fmaf(a.w, w3.w, acc[i][3]))));
        }
    }
    __syncthreads();  // everyone done reading Xs/Ws

    float4 bb = *(const float4*)(fb2 + cx);
#pragma unroll
    for (int i = 0; i < 4; i++) {
        Xs[(ry + i) * 64 + cx + 0] = acc[i][0] + bb.x;
        Xs[(ry + i) * 64 + cx + 1] = acc[i][1] + bb.y;
        Xs[(ry + i) * 64 + cx + 2] = acc[i][2] + bb.z;
        Xs[(ry + i) * 64 + cx + 3] = acc[i][3] + bb.w;
    }
#pragma unroll
    for (int t = 0; t < 8; t++) Ws[tid + t * 256] = ow[tid + t * 256];  // 64x32
    if (tid < 128) Ws[2048 + tid] = cw[tid];                             // 64x2
    __syncthreads();

    int c = tid & 31;
    int rb = (tid >> 5) * 8;
    for (int rr = 0; rr < 8; rr++) {
        int r = rb + rr;
        float a = __ldg(ob + c);
#pragma unroll 16
        for (int k = 0; k < 64; k++) a += Xs[r * 64 + k] * Ws[k * 32 + c];
        if (row0 + r < Nn) outF[(size_t)(row0 + r) * 32 + c] = a;
    }
    if (tid < 128) {
        int r = tid >> 1, cc = tid & 1;
        float a = __ldg(cb + cc);
#pragma unroll 16
        for (int k = 0; k < 64; k++) a += Xs[r * 64 + k] * Ws[2048 + k * 2 + cc];
        if (row0 + r < Nn) outT[(size_t)(row0 + r) * 2 + cc] = a;
    }
}

// ---------------------------------------------------------------------------
extern "C" void kernel_launch(void* const* d_in, const int* in_sizes, int n_in,
                              void* d_out, int out_size) {
    const float* xin[2] = {(const float*)d_in[0], (const float*)d_in[1]};
    const int* ei[2]    = {(const int*)d_in[2], (const int*)d_in[3]};
    const float* ew1[2] = {(const float*)d_in[4],  (const float*)d_in[10]};
    const float* eb1[2] = {(const float*)d_in[5],  (const float*)d_in[11]};
    const float* ew2[2] = {(const float*)d_in[6],  (const float*)d_in[12]};
    const float* eb2[2] = {(const float*)d_in[7],  (const float*)d_in[13]};
    const float* cw[2]  = {(const float*)d_in[8],  (const float*)d_in[14]};
    const float* cb[2]  = {(const float*)d_in[9],  (const float*)d_in[15]};
    const float* fw1 = (const float*)d_in[16];
    const float* fb1 = (const float*)d_in[17];
    const float* fw2 = (const float*)d_in[18];
    const float* fb2 = (const float*)d_in[19];
    const float* ow  = (const float*)d_in[20];
    const float* obv = (const float*)d_in[21];
    const float* clw = (const float*)d_in[22];
    const float* clb = (const float*)d_in[23];

    float *Hb, *Yb, *Xb, *Ab, *Db, *Wp, *bp;
    cudaGetSymbolAddress((void**)&Hb, g_H);
    cudaGetSymbolAddress((void**)&Yb, g_Yb);
    cudaGetSymbolAddress((void**)&Xb, g_Xb);
    cudaGetSymbolAddress((void**)&Ab, g_Ab);
    cudaGetSymbolAddress((void**)&Db, g_D);
    cudaGetSymbolAddress((void**)&Wp, g_Wp);
    cudaGetSymbolAddress((void**)&bp, g_bp);
    float* H[2] = {Hb, Hb + (size_t)Nn * 64};
    float* Y[2] = {Yb, Yb + (size_t)Nn * 64};
    float* X[2] = {Xb, Xb + (size_t)Nn * 64};
    float* A[2][3];
    for (int g = 0; g < 2; g++)
        for (int l = 0; l < 3; l++) A[g][l] = Ab + (size_t)(g * 3 + l) * Nn * 64;
    float* D[2] = {Db, Db + Nn};

    // ---- prologue ----
    cudaMemsetAsync(Ab, 0, 6 * NB);                 // all agg buffers
    cudaMemsetAsync(Db, 0, 2 * Nn * sizeof(float));
    deg_count_k<<<(Ee + 255) / 256, 256>>>(ei[0], ei[1], D[0], D[1]);
    dinv_k<<<(Nn + 255) / 256, 256>>>(D[0], D[1]);
    prep_k<<<2, 256>>>(ew2[0], eb2[0], cw[0], ew2[1], eb2[1], cw[1], Wp, bp);
    enc2_k<<<dim3((Nn * 64 + 255) / 256, 2), 256>>>(xin[0], ew1[0], eb1[0],
                                                    xin[1], ew1[1], eb1[1], Hb);

    const dim3 GRID_G(GB2);            // gemm-only
    const dim3 GRID_C(GB2 + SB);       // gemm + scatter

    // stage2: y0(g0) = (H0 @ Wp0 + bp0) * dinv0
    combo_k<<<GRID_G, 256>>>(GB2, H[0], nullptr, nullptr, nullptr, Wp, bp, D[0], Y[0],
                             0, 0, nullptr, nullptr, nullptr);
    // stage3: y0(g1) || scatter(Y0 -> A[0][0])
    combo_k<<<GRID_C, 256>>>(GB2, H[1], nullptr, nullptr, nullptr, Wp + 4096, bp + 64, D[1], Y[1],
                             0, 0, Y[0], ei[0], A[0][0]);
    // stage4: gemmL1(g0): relu-gcn(Y0,A00) @ cw0[1] * dinv -> X0 || scatter(Y1 -> A[1][0])
    combo_k<<<GRID_C, 256>>>(GB2, Y[0], A[0][0], D[0], cb[0], cw[0] + 4096, nullptr, D[0], X[0],
                             1, 0, Y[1], ei[1], A[1][0]);
    // stage5: gemmL1(g1) -> X1 || scatter(X0 -> A[0][1])
    combo_k<<<GRID_C, 256>>>(GB2, Y[1], A[1][0], D[1], cb[1], cw[1] + 4096, nullptr, D[1], X[1],
                             1, 0, X[0], ei[0], A[0][1]);
    // stage6: gemmL2(g0): relu-gcn(X0,A01) @ cw0[2] * dinv -> Y0 || scatter(X1 -> A[1][1])
    combo_k<<<GRID_C, 256>>>(GB2, X[0], A[0][1], D[0], cb[0] + 64, cw[0] + 8192, nullptr, D[0], Y[0],
                             1, 0, X[1], ei[1], A[1][1]);
    // stage7: gemmL2(g1) -> Y1 || scatter(Y0 -> A[0][2])
    combo_k<<<GRID_C, 256>>>(GB2, X[1], A[1][1], D[1], cb[1] + 64, cw[1] + 8192, nullptr, D[1], Y[1],
                             1, 0, Y[0], ei[0], A[0][2]);
    // stage8: fusion1a(g0): relu-gcn(Y0,A02) @ fw1[0:64] + fb1 -> F(=H0) || scatter(Y1 -> A[1][2])
    combo_k<<<GRID_C, 256>>>(GB2, Y[0], A[0][2], D[0], cb[0] + 128, fw1, fb1, nullptr, H[0],
                             1, 0, Y[1], ei[1], A[1][2]);
    // stage9: fusion1b(g1): relu-gcn(Y1,A12) @ fw1[64:128] accum -> F
    combo_k<<<GRID_G, 256>>>(GB2, Y[1], A[1][2], D[1], cb[1] + 128, fw1 + 4096, nullptr, nullptr, H[0],
                             1, 1, nullptr, nullptr, nullptr);

    // stage10: fusion layer 2 + both output heads
    head_k<<<(Nn + 63) / 64, 256>>>(H[0], fw2, fb2, ow, obv, clw, clb,
                                    (float*)d_out, (float*)d_out + (size_t)Nn * 32);
}

// round 4
// speedup vs baseline: 1.1485x; 1.1485x over previous
#include <cuda_runtime.h>

#define Nn 100000
#define Ee 1000000
#define NB ((size_t)Nn * 64 * sizeof(float))
#define GB2 ((Nn + 127) / 128)     /* 782 gemm blocks */

// Scratch (device globals — no runtime allocation allowed)
__device__ float g_Yb[2][(size_t)Nn * 64];
__device__ float g_Xb[2][(size_t)Nn * 64];
__device__ float g_Fb[(size_t)Nn * 64];
__device__ float g_Ab[6][(size_t)Nn * 64];  // agg: [g*3 + layer]
__device__ float g_D[2][Nn];
__device__ float g_Wp[2][64 * 64];          // w2 @ W0
__device__ float g_bp[2][64];               // b2 @ W0

// ---------------------------------------------------------------------------
// Tiny precompute: Wp[g] = w2 @ cw[0];  bp[g] = b2 @ cw[0]
// ---------------------------------------------------------------------------
__global__ void prep_k(const float* __restrict__ w2a, const float* __restrict__ b2a,
                       const float* __restrict__ cwa,
                       const float* __restrict__ w2b, const float* __restrict__ b2b,
                       const float* __restrict__ cwb,
                       float* __restrict__ wp, float* __restrict__ bp) {
    int g = blockIdx.x;
    const float* w2 = g ? w2b : w2a;
    const float* b2 = g ? b2b : b2a;
    const float* cw = g ? cwb : cwa;
    __shared__ float A[4096], B[4096];
    int tid = threadIdx.x;
#pragma unroll
    for (int t = 0; t < 16; t++) {
        A[tid + t * 256] = w2[tid + t * 256];
        B[tid + t * 256] = cw[tid + t * 256];
    }
    __syncthreads();
    float* WP = wp + g * 4096;
#pragma unroll
    for (int t = 0; t < 16; t++) {
        int idx = tid + t * 256;
        int i = idx >> 6, j = idx & 63;
        float s = 0.f;
#pragma unroll 16
        for (int k = 0; k < 64; k++) s = fmaf(A[i * 64 + k], B[k * 64 + j], s);
        WP[idx] = s;
    }
    if (tid < 64) {
        float s = 0.f;
        for (int k = 0; k < 64; k++) s = fmaf(b2[k], B[k * 64 + tid], s);
        bp[g * 64 + tid] = s;
    }
}

// ---------------------------------------------------------------------------
// Degree: deg[dst] += 1 per edge; then dinv = rsqrt(deg + 1)  (self-loop)
// ---------------------------------------------------------------------------
__global__ void deg_count_k(const int* __restrict__ f, const int* __restrict__ s,
                            float* __restrict__ d0, float* __restrict__ d1) {
    int e = blockIdx.x * blockDim.x + threadIdx.x;
    if (e < Ee) {
        atomicAdd(d0 + __ldg(f + Ee + e), 1.f);
        atomicAdd(d1 + __ldg(s + Ee + e), 1.f);
    }
}

__global__ void dinv_k(float* __restrict__ d0, float* __restrict__ d1) {
    int i = blockIdx.x * blockDim.x + threadIdx.x;
    if (i < Nn) {
        d0[i] = rsqrtf(d0[i] + 1.f);
        d1[i] = rsqrtf(d1[i] + 1.f);
    }
}

// ---------------------------------------------------------------------------
// 128x64 GEMM tile, 512 threads, 4x4 register blocking, all-float4 LDS.
// Input modes (mode):
//   0: v = inA[r,c]                                  (raw [N,64] input)
//   1: v = relu(dinv[r]*(inAgg[r,c]+inA[r,c]) + inBias[c])   (fused GCN epilogue)
//   2: v = relu(b1[c] + sum_{k<4} x[r,k]*w1[k,c])    (fused encoder hidden;
//            inA = x [N,4], inAgg = w1 [4,64], inBias = b1 [64])
// Output: out[r,c] (+= if accum) (acc + outBias[c]) * (outDinv ? dinv[r] : 1)
// ---------------------------------------------------------------------------
__global__ __launch_bounds__(512, 2) void gemm128_k(
    const float* __restrict__ inA, const float* __restrict__ inAgg,
    const float* __restrict__ inDinv, const float* __restrict__ inBias,
    const float* __restrict__ W, const float* __restrict__ outBias,
    const float* __restrict__ outDinv, float* __restrict__ out,
    int mode, int accum) {
    __shared__ float Xs[128 * 64];   // 32 KB
    __shared__ float Ws[64 * 64];    // 16 KB
    __shared__ float W1s[256];
    __shared__ float B1s[64];

    int tid = threadIdx.x;
    int row0 = blockIdx.x * 128;

    // Load W (1024 float4) — 2 per thread
    const float4* W4 = (const float4*)W;
    ((float4*)Ws)[tid]       = __ldg(W4 + tid);
    ((float4*)Ws)[tid + 512] = __ldg(W4 + tid + 512);

    if (mode == 2) {
        if (tid < 256) W1s[tid] = __ldg(inAgg + tid);
        if (tid < 64)  B1s[tid] = __ldg(inBias + tid);
        __syncthreads();   // W1s/B1s ready before Xs fill uses them
    }

    // Fill X tile (2048 float4) — 4 per thread
#pragma unroll
    for (int t = 0; t < 4; t++) {
        int lin = tid + t * 512;        // float4 index; row = lin>>4, col4 = lin&15
        int r = lin >> 4;
        float4 v = make_float4(0.f, 0.f, 0.f, 0.f);
        if (row0 + r < Nn) {
            if (mode == 0) {
                v = ((const float4*)inA)[(size_t)(row0 + r) * 16 + (lin & 15)];
            } else if (mode == 1) {
                size_t idx = (size_t)(row0 + r) * 16 + (lin & 15);
                float4 a = ((const float4*)inA)[idx];
                float4 g = ((const float4*)inAgg)[idx];
                float dv = inDinv[row0 + r];
                float4 b = __ldg((const float4*)inBias + (lin & 15));
                v.x = fmaxf(fmaf(dv, g.x + a.x, b.x), 0.f);
                v.y = fmaxf(fmaf(dv, g.y + a.y, b.y), 0.f);
                v.z = fmaxf(fmaf(dv, g.z + a.z, b.z), 0.f);
                v.w = fmaxf(fmaf(dv, g.w + a.w, b.w), 0.f);
            } else {
                float4 xv = __ldg((const float4*)inA + (row0 + r));
                int c = (lin & 15) * 4;
                v.x = fmaxf(B1s[c+0] + xv.x*W1s[c+0] + xv.y*W1s[64+c+0] + xv.z*W1s[128+c+0] + xv.w*W1s[192+c+0], 0.f);
                v.y = fmaxf(B1s[c+1] + xv.x*W1s[c+1] + xv.y*W1s[64+c+1] + xv.z*W1s[128+c+1] + xv.w*W1s[192+c+1], 0.f);
                v.z = fmaxf(B1s[c+2] + xv.x*W1s[c+2] + xv.y*W1s[64+c+2] + xv.z*W1s[128+c+2] + xv.w*W1s[192+c+2], 0.f);
                v.w = fmaxf(B1s[c+3] + xv.x*W1s[c+3] + xv.y*W1s[64+c+3] + xv.z*W1s[128+c+3] + xv.w*W1s[192+c+3], 0.f);
            }
        }
        ((float4*)Xs)[lin] = v;
    }
    __syncthreads();

    int cx = (tid & 15) * 4;   // output column base
    int ry = (tid >> 4) * 4;   // output row base (4 rows per thread, 32 groups)
    float acc[4][4];
#pragma unroll
    for (int i = 0; i < 4; i++)
#pragma unroll
        for (int j = 0; j < 4; j++) acc[i][j] = 0.f;

#pragma unroll
    for (int k0 = 0; k0 < 64; k0 += 4) {
        float4 w0 = *(const float4*)(Ws + (k0 + 0) * 64 + cx);
        float4 w1 = *(const float4*)(Ws + (k0 + 1) * 64 + cx);
        float4 w2 = *(const float4*)(Ws + (k0 + 2) * 64 + cx);
        float4 w3 = *(const float4*)(Ws + (k0 + 3) * 64 + cx);
#pragma unroll
        for (int i = 0; i < 4; i++) {
            float4 a = *(const float4*)(Xs + (ry + i) * 64 + k0);
            acc[i][0] = fmaf(a.x, w0.x, fmaf(a.y, w1.x, fmaf(a.z, w2.x, fmaf(a.w, w3.x, acc[i][0]))));
            acc[i][1] = fmaf(a.x, w0.y, fmaf(a.y, w1.y, fmaf(a.z, w2.y, fmaf(a.w, w3.y, acc[i][1]))));
            acc[i][2] = fmaf(a.x, w0.z, fmaf(a.y, w1.z, fmaf(a.z, w2.z, fmaf(a.w, w3.z, acc[i][2]))));
            acc[i][3] = fmaf(a.x, w0.w, fmaf(a.y, w1.w, fmaf(a.z, w2.w, fmaf(a.w, w3.w, acc[i][3]))));
        }
    }

    float4 obv = outBias ? __ldg((const float4*)(outBias + cx))
                         : make_float4(0.f, 0.f, 0.f, 0.f);
#pragma unroll
    for (int i = 0; i < 4; i++) {
        int r = row0 + ry + i;
        if (r < Nn) {
            float sc = outDinv ? outDinv[r] : 1.f;
            float4 o = make_float4((acc[i][0] + obv.x) * sc, (acc[i][1] + obv.y) * sc,
                                   (acc[i][2] + obv.z) * sc, (acc[i][3] + obv.w) * sc);
            float* p = out + (size_t)r * 64 + cx;
            if (accum) {
                float4 pv = *(const float4*)p;
                o.x += pv.x; o.y += pv.y; o.z += pv.z; o.w += pv.w;
            }
            *(float4*)p = o;
        }
    }
}

// ---------------------------------------------------------------------------
// Edge scatter: agg[dst, :] += y[src, :]   (16 threads/edge, float4 red ops)
// ---------------------------------------------------------------------------
__global__ __launch_bounds__(256) void scatter_k(const float* __restrict__ y,
                                                 const int* __restrict__ ei,
                                                 float* __restrict__ agg) {
    int t = blockIdx.x * blockDim.x + threadIdx.x;
    int e = t >> 4;
    if (e >= Ee) return;
    int j = (t & 15) * 4;
    int src = __ldg(ei + e);
    int dst = __ldg(ei + Ee + e);
    float4 v = *(const float4*)(y + (size_t)src * 64 + j);
    atomicAdd((float4*)(agg + (size_t)dst * 64 + j), v);
}

// ---------------------------------------------------------------------------
// Head: fused = relu(h1) @ fw2 + fb2; feats = fused@ow+ob; types = fused@cw+cb
// ---------------------------------------------------------------------------
__global__ __launch_bounds__(256) void head_k(
    const float* __restrict__ h1, const float* __restrict__ fw2, const float* __restrict__ fb2,
    const float* __restrict__ ow, const float* __restrict__ ob,
    const float* __restrict__ cw, const float* __restrict__ cb,
    float* __restrict__ outF, float* __restrict__ outT) {
    __shared__ float Xs[64 * 64];
    __shared__ float Ws[64 * 64];
    int tid = threadIdx.x;
    int row0 = blockIdx.x * 64;
    size_t base = (size_t)row0 * 64;

#pragma unroll
    for (int t = 0; t < 16; t++) Ws[tid + t * 256] = fw2[tid + t * 256];
#pragma unroll
    for (int t = 0; t < 16; t++) {
        int lin = tid + t * 256;
        int r = lin >> 6;
        Xs[lin] = (row0 + r < Nn) ? fmaxf(h1[base + lin], 0.f) : 0.f;
    }
    __syncthreads();

    int cx = (tid & 15) * 4;
    int ry = (tid >> 4) * 4;
    float acc[4][4];
#pragma unroll
    for (int i = 0; i < 4; i++)
#pragma unroll
        for (int j = 0; j < 4; j++) acc[i][j] = 0.f;

#pragma unroll
    for (int k0 = 0; k0 < 64; k0 += 4) {
        float4 w0 = *(const float4*)(Ws + (k0 + 0) * 64 + cx);
        float4 w1 = *(const float4*)(Ws + (k0 + 1) * 64 + cx);
        float4 w2 = *(const float4*)(Ws + (k0 + 2) * 64 + cx);
        float4 w3 = *(const float4*)(Ws + (k0 + 3) * 64 + cx);
#pragma unroll
        for (int i = 0; i < 4; i++) {
            float4 a = *(const float4*)(Xs + (ry + i) * 64 + k0);
            acc[i][0] = fmaf(a.x, w0.x, fmaf(a.y, w1.x, fmaf(a.z, w2.x, fmaf(a.w, w3.x, acc[i][0]))));
            acc[i][1] = fmaf(a.x, w0.y, fmaf(a.y, w1.y, fmaf(a.z, w2.y, fmaf(a.w, w3.y, acc[i][1]))));
            acc[i][2] = fmaf(a.x, w0.z, fmaf(a.y, w1.z, fmaf(a.z, w2.z, fmaf(a.w, w3.z, acc[i][2]))));
            acc[i][3] = fmaf(a.x, w0.w, fmaf(a.y, w1.w, fmaf(a.z, w2.w, fmaf(a.w, w3.w, acc[i][3]))));
        }
    }
    __syncthreads();  // everyone done reading Xs/Ws

    float4 bb = *(const float4*)(fb2 + cx);
#pragma unroll
    for (int i = 0; i < 4; i++) {
        Xs[(ry + i) * 64 + cx + 0] = acc[i][0] + bb.x;
        Xs[(ry + i) * 64 + cx + 1] = acc[i][1] + bb.y;
        Xs[(ry + i) * 64 + cx + 2] = acc[i][2] + bb.z;
        Xs[(ry + i) * 64 + cx + 3] = acc[i][3] + bb.w;
    }
#pragma unroll
    for (int t = 0; t < 8; t++) Ws[tid + t * 256] = ow[tid + t * 256];  // 64x32
    if (tid < 128) Ws[2048 + tid] = cw[tid];                             // 64x2
    __syncthreads();

    int c = tid & 31;
    int rb = (tid >> 5) * 8;
    for (int rr = 0; rr < 8; rr++) {
        int r = rb + rr;
        float a = __ldg(ob + c);
#pragma unroll 16
        for (int k = 0; k < 64; k++) a += Xs[r * 64 + k] * Ws[k * 32 + c];
        if (row0 + r < Nn) outF[(size_t)(row0 + r) * 32 + c] = a;
    }
    if (tid < 128) {
        int r = tid >> 1, cc = tid & 1;
        float a = __ldg(cb + cc);
#pragma unroll 16
        for (int k = 0; k < 64; k++) a += Xs[r * 64 + k] * Ws[2048 + k * 2 + cc];
        if (row0 + r < Nn) outT[(size_t)(row0 + r) * 2 + cc] = a;
    }
}

// ---------------------------------------------------------------------------
extern "C" void kernel_launch(void* const* d_in, const int* in_sizes, int n_in,
                              void* d_out, int out_size) {
    const float* xin[2] = {(const float*)d_in[0], (const float*)d_in[1]};
    const int* ei[2]    = {(const int*)d_in[2], (const int*)d_in[3]};
    const float* ew1[2] = {(const float*)d_in[4],  (const float*)d_in[10]};
    const float* eb1[2] = {(const float*)d_in[5],  (const float*)d_in[11]};
    const float* ew2[2] = {(const float*)d_in[6],  (const float*)d_in[12]};
    const float* eb2[2] = {(const float*)d_in[7],  (const float*)d_in[13]};
    const float* cw[2]  = {(const float*)d_in[8],  (const float*)d_in[14]};
    const float* cb[2]  = {(const float*)d_in[9],  (const float*)d_in[15]};
    const float* fw1 = (const float*)d_in[16];
    const float* fb1 = (const float*)d_in[17];
    const float* fw2 = (const float*)d_in[18];
    const float* fb2 = (const float*)d_in[19];
    const float* ow  = (const float*)d_in[20];
    const float* obv = (const float*)d_in[21];
    const float* clw = (const float*)d_in[22];
    const float* clb = (const float*)d_in[23];

    float *Yb, *Xb, *Fb, *Ab, *Db, *Wp, *bp;
    cudaGetSymbolAddress((void**)&Yb, g_Yb);
    cudaGetSymbolAddress((void**)&Xb, g_Xb);
    cudaGetSymbolAddress((void**)&Fb, g_Fb);
    cudaGetSymbolAddress((void**)&Ab, g_Ab);
    cudaGetSymbolAddress((void**)&Db, g_D);
    cudaGetSymbolAddress((void**)&Wp, g_Wp);
    cudaGetSymbolAddress((void**)&bp, g_bp);
    float* Y[2] = {Yb, Yb + (size_t)Nn * 64};
    float* X[2] = {Xb, Xb + (size_t)Nn * 64};
    float* A[2][3];
    for (int g = 0; g < 2; g++)
        for (int l = 0; l < 3; l++) A[g][l] = Ab + (size_t)(g * 3 + l) * Nn * 64;
    float* D[2] = {Db, Db + Nn};

    // ---- prologue ----
    cudaMemsetAsync(Ab, 0, 6 * NB);                 // all agg buffers
    cudaMemsetAsync(Db, 0, 2 * Nn * sizeof(float));
    deg_count_k<<<(Ee + 255) / 256, 256>>>(ei[0], ei[1], D[0], D[1]);
    dinv_k<<<(Nn + 255) / 256, 256>>>(D[0], D[1]);
    prep_k<<<2, 256>>>(ew2[0], eb2[0], cw[0], ew2[1], eb2[1], cw[1], Wp, bp);

    const int SG = (Ee * 16) / 256;

    for (int g = 0; g < 2; g++) {
        // Fused front: Y = relu(x@w1+b1) @ Wp + bp, scaled by dinv   (mode 2)
        gemm128_k<<<GB2, 512>>>(xin[g], ew1[g], nullptr, eb1[g],
                                Wp + g * 4096, bp + g * 64, D[g], Y[g], 2, 0);
        scatter_k<<<SG, 256>>>(Y[g], ei[g], A[g][0]);

        // GCN layer 1: relu-gcn(Y, A0) @ cw[1] * dinv -> X
        gemm128_k<<<GB2, 512>>>(Y[g], A[g][0], D[g], cb[g],
                                cw[g] + 4096, nullptr, D[g], X[g], 1, 0);
        scatter_k<<<SG, 256>>>(X[g], ei[g], A[g][1]);

        // GCN layer 2: relu-gcn(X, A1) @ cw[2] * dinv -> Y
        gemm128_k<<<GB2, 512>>>(X[g], A[g][1], D[g], cb[g] + 64,
                                cw[g] + 8192, nullptr, D[g], Y[g], 1, 0);
        scatter_k<<<SG, 256>>>(Y[g], ei[g], A[g][2]);
    }

    // Fusion layer 1 (K=128 via two accumulating K=64 passes) -> F
    gemm128_k<<<GB2, 512>>>(Y[0], A[0][2], D[0], cb[0] + 128, fw1, fb1, nullptr, Fb, 1, 0);
    gemm128_k<<<GB2, 512>>>(Y[1], A[1][2], D[1], cb[1] + 128, fw1 + 4096, nullptr, nullptr, Fb, 1, 1);

    // Fusion layer 2 + both output heads
    head_k<<<(Nn + 63) / 64, 256>>>(Fb, fw2, fb2, ow, obv, clw, clb,
                                    (float*)d_out, (float*)d_out + (size_t)Nn * 32);
}

// round 5
// speedup vs baseline: 1.1546x; 1.0053x over previous
#include <cuda_runtime.h>

#define Nn 100000
#define Ee 1000000
#define NB ((size_t)Nn * 64 * sizeof(float))
#define GB2 ((Nn + 127) / 128)     /* 782 gemm blocks */

// Scratch (device globals — no runtime allocation allowed)
__device__ float g_Yb[2][(size_t)Nn * 64];
__device__ float g_Xb[2][(size_t)Nn * 64];
__device__ float g_Fb[(size_t)Nn * 64];
__device__ float g_Ab[6][(size_t)Nn * 64];  // agg: [g*3 + layer]
__device__ float g_D[2][Nn];
__device__ float g_Wp[2][64 * 64];          // w2 @ W0
__device__ float g_bp[2][64];               // b2 @ W0

// ---------------------------------------------------------------------------
// Tiny precompute: Wp[g] = w2 @ cw[0];  bp[g] = b2 @ cw[0]
// ---------------------------------------------------------------------------
__global__ void prep_k(const float* __restrict__ w2a, const float* __restrict__ b2a,
                       const float* __restrict__ cwa,
                       const float* __restrict__ w2b, const float* __restrict__ b2b,
                       const float* __restrict__ cwb,
                       float* __restrict__ wp, float* __restrict__ bp) {
    int g = blockIdx.x;
    const float* w2 = g ? w2b : w2a;
    const float* b2 = g ? b2b : b2a;
    const float* cw = g ? cwb : cwa;
    __shared__ float A[4096], B[4096];
    int tid = threadIdx.x;
#pragma unroll
    for (int t = 0; t < 16; t++) {
        A[tid + t * 256] = w2[tid + t * 256];
        B[tid + t * 256] = cw[tid + t * 256];
    }
    __syncthreads();
    float* WP = wp + g * 4096;
#pragma unroll
    for (int t = 0; t < 16; t++) {
        int idx = tid + t * 256;
        int i = idx >> 6, j = idx & 63;
        float s = 0.f;
#pragma unroll 16
        for (int k = 0; k < 64; k++) s = fmaf(A[i * 64 + k], B[k * 64 + j], s);
        WP[idx] = s;
    }
    if (tid < 64) {
        float s = 0.f;
        for (int k = 0; k < 64; k++) s = fmaf(b2[k], B[k * 64 + tid], s);
        bp[g * 64 + tid] = s;
    }
}

// ---------------------------------------------------------------------------
// Degree: deg[dst] += 1 per edge; then dinv = rsqrt(deg + 1)  (self-loop)
// ---------------------------------------------------------------------------
__global__ void deg_count_k(const int* __restrict__ f, const int* __restrict__ s,
                            float* __restrict__ d0, float* __restrict__ d1) {
    int e = blockIdx.x * blockDim.x + threadIdx.x;
    if (e < Ee) {
        atomicAdd(d0 + __ldg(f + Ee + e), 1.f);
        atomicAdd(d1 + __ldg(s + Ee + e), 1.f);
    }
}

__global__ void dinv_k(float* __restrict__ d0, float* __restrict__ d1) {
    int i = blockIdx.x * blockDim.x + threadIdx.x;
    if (i < Nn) {
        d0[i] = rsqrtf(d0[i] + 1.f);
        d1[i] = rsqrtf(d1[i] + 1.f);
    }
}

// ---------------------------------------------------------------------------
// 128x64 GEMM tile, 512 threads, 4x4 register blocking, all-float4 LDS.
// Input modes (mode):
//   0: v = inA[r,c]
//   1: v = relu(dinv[r]*(inAgg[r,c]+inA[r,c]) + inBias[c])   (fused GCN epilogue)
//   2: v = relu(b1[c] + sum_{k<4} x[r,k]*w1[k,c])            (fused encoder)
// Output: out[r,c] (+= if accum) (acc + outBias[c]) * (outDinv ? dinv[r] : 1)
// ---------------------------------------------------------------------------
__global__ __launch_bounds__(512, 2) void gemm128_k(
    const float* __restrict__ inA, const float* __restrict__ inAgg,
    const float* __restrict__ inDinv, const float* __restrict__ inBias,
    const float* __restrict__ W, const float* __restrict__ outBias,
    const float* __restrict__ outDinv, float* __restrict__ out,
    int mode, int accum) {
    __shared__ float Xs[128 * 64];   // 32 KB
    __shared__ float Ws[64 * 64];    // 16 KB
    __shared__ float W1s[256];
    __shared__ float B1s[64];

    int tid = threadIdx.x;
    int row0 = blockIdx.x * 128;

    const float4* W4 = (const float4*)W;
    ((float4*)Ws)[tid]       = __ldg(W4 + tid);
    ((float4*)Ws)[tid + 512] = __ldg(W4 + tid + 512);

    if (mode == 2) {
        if (tid < 256) W1s[tid] = __ldg(inAgg + tid);
        if (tid < 64)  B1s[tid] = __ldg(inBias + tid);
        __syncthreads();
    }

#pragma unroll
    for (int t = 0; t < 4; t++) {
        int lin = tid + t * 512;
        int r = lin >> 4;
        float4 v = make_float4(0.f, 0.f, 0.f, 0.f);
        if (row0 + r < Nn) {
            if (mode == 0) {
                v = ((const float4*)inA)[(size_t)(row0 + r) * 16 + (lin & 15)];
            } else if (mode == 1) {
                size_t idx = (size_t)(row0 + r) * 16 + (lin & 15);
                float4 a = ((const float4*)inA)[idx];
                float4 g = ((const float4*)inAgg)[idx];
                float dv = inDinv[row0 + r];
                float4 b = __ldg((const float4*)inBias + (lin & 15));
                v.x = fmaxf(fmaf(dv, g.x + a.x, b.x), 0.f);
                v.y = fmaxf(fmaf(dv, g.y + a.y, b.y), 0.f);
                v.z = fmaxf(fmaf(dv, g.z + a.z, b.z), 0.f);
                v.w = fmaxf(fmaf(dv, g.w + a.w, b.w), 0.f);
            } else {
                float4 xv = __ldg((const float4*)inA + (row0 + r));
                int c = (lin & 15) * 4;
                v.x = fmaxf(B1s[c+0] + xv.x*W1s[c+0] + xv.y*W1s[64+c+0] + xv.z*W1s[128+c+0] + xv.w*W1s[192+c+0], 0.f);
                v.y = fmaxf(B1s[c+1] + xv.x*W1s[c+1] + xv.y*W1s[64+c+1] + xv.z*W1s[128+c+1] + xv.w*W1s[192+c+1], 0.f);
                v.z = fmaxf(B1s[c+2] + xv.x*W1s[c+2] + xv.y*W1s[64+c+2] + xv.z*W1s[128+c+2] + xv.w*W1s[192+c+2], 0.f);
                v.w = fmaxf(B1s[c+3] + xv.x*W1s[c+3] + xv.y*W1s[64+c+3] + xv.z*W1s[128+c+3] + xv.w*W1s[192+c+3], 0.f);
            }
        }
        ((float4*)Xs)[lin] = v;
    }
    __syncthreads();

    int cx = (tid & 15) * 4;
    int ry = (tid >> 4) * 4;
    float acc[4][4];
#pragma unroll
    for (int i = 0; i < 4; i++)
#pragma unroll
        for (int j = 0; j < 4; j++) acc[i][j] = 0.f;

#pragma unroll
    for (int k0 = 0; k0 < 64; k0 += 4) {
        float4 w0 = *(const float4*)(Ws + (k0 + 0) * 64 + cx);
        float4 w1 = *(const float4*)(Ws + (k0 + 1) * 64 + cx);
        float4 w2 = *(const float4*)(Ws + (k0 + 2) * 64 + cx);
        float4 w3 = *(const float4*)(Ws + (k0 + 3) * 64 + cx);
#pragma unroll
        for (int i = 0; i < 4; i++) {
            float4 a = *(const float4*)(Xs + (ry + i) * 64 + k0);
            acc[i][0] = fmaf(a.x, w0.x, fmaf(a.y, w1.x, fmaf(a.z, w2.x, fmaf(a.w, w3.x, acc[i][0]))));
            acc[i][1] = fmaf(a.x, w0.y, fmaf(a.y, w1.y, fmaf(a.z, w2.y, fmaf(a.w, w3.y, acc[i][1]))));
            acc[i][2] = fmaf(a.x, w0.z, fmaf(a.y, w1.z, fmaf(a.z, w2.z, fmaf(a.w, w3.z, acc[i][2]))));
            acc[i][3] = fmaf(a.x, w0.w, fmaf(a.y, w1.w, fmaf(a.z, w2.w, fmaf(a.w, w3.w, acc[i][3]))));
        }
    }

    float4 obv = outBias ? __ldg((const float4*)(outBias + cx))
                         : make_float4(0.f, 0.f, 0.f, 0.f);
#pragma unroll
    for (int i = 0; i < 4; i++) {
        int r = row0 + ry + i;
        if (r < Nn) {
            float sc = outDinv ? outDinv[r] : 1.f;
            float4 o = make_float4((acc[i][0] + obv.x) * sc, (acc[i][1] + obv.y) * sc,
                                   (acc[i][2] + obv.z) * sc, (acc[i][3] + obv.w) * sc);
            float* p = out + (size_t)r * 64 + cx;
            if (accum) {
                float4 pv = *(const float4*)p;
                o.x += pv.x; o.y += pv.y; o.z += pv.z; o.w += pv.w;
            }
            *(float4*)p = o;
        }
    }
}

// ---------------------------------------------------------------------------
// Edge scatter: agg[dst, :] += y[src, :]   (16 threads/edge, float4 red ops)
// ---------------------------------------------------------------------------
__global__ __launch_bounds__(256) void scatter_k(const float* __restrict__ y,
                                                 const int* __restrict__ ei,
                                                 float* __restrict__ agg) {
    int t = blockIdx.x * blockDim.x + threadIdx.x;
    int e = t >> 4;
    if (e >= Ee) return;
    int j = (t & 15) * 4;
    int src = __ldg(ei + e);
    int dst = __ldg(ei + Ee + e);
    float4 v = *(const float4*)(y + (size_t)src * 64 + j);
    atomicAdd((float4*)(agg + (size_t)dst * 64 + j), v);
}

// ---------------------------------------------------------------------------
// Head: fused = relu(h1) @ fw2 + fb2; feats = fused@ow+ob; types = fused@cw+cb
// ---------------------------------------------------------------------------
__global__ __launch_bounds__(256) void head_k(
    const float* __restrict__ h1, const float* __restrict__ fw2, const float* __restrict__ fb2,
    const float* __restrict__ ow, const float* __restrict__ ob,
    const float* __restrict__ cw, const float* __restrict__ cb,
    float* __restrict__ outF, float* __restrict__ outT) {
    __shared__ float Xs[64 * 64];
    __shared__ float Ws[64 * 64];
    int tid = threadIdx.x;
    int row0 = blockIdx.x * 64;
    size_t base = (size_t)row0 * 64;

#pragma unroll
    for (int t = 0; t < 16; t++) Ws[tid + t * 256] = fw2[tid + t * 256];
#pragma unroll
    for (int t = 0; t < 16; t++) {
        int lin = tid + t * 256;
        int r = lin >> 6;
        Xs[lin] = (row0 + r < Nn) ? fmaxf(h1[base + lin], 0.f) : 0.f;
    }
    __syncthreads();

    int cx = (tid & 15) * 4;
    int ry = (tid >> 4) * 4;
    float acc[4][4];
#pragma unroll
    for (int i = 0; i < 4; i++)
#pragma unroll
        for (int j = 0; j < 4; j++) acc[i][j] = 0.f;

#pragma unroll
    for (int k0 = 0; k0 < 64; k0 += 4) {
        float4 w0 = *(const float4*)(Ws + (k0 + 0) * 64 + cx);
        float4 w1 = *(const float4*)(Ws + (k0 + 1) * 64 + cx);
        float4 w2 = *(const float4*)(Ws + (k0 + 2) * 64 + cx);
        float4 w3 = *(const float4*)(Ws + (k0 + 3) * 64 + cx);
#pragma unroll
        for (int i = 0; i < 4; i++) {
            float4 a = *(const float4*)(Xs + (ry + i) * 64 + k0);
            acc[i][0] = fmaf(a.x, w0.x, fmaf(a.y, w1.x, fmaf(a.z, w2.x, fmaf(a.w, w3.x, acc[i][0]))));
            acc[i][1] = fmaf(a.x, w0.y, fmaf(a.y, w1.y, fmaf(a.z, w2.y, fmaf(a.w, w3.y, acc[i][1]))));
            acc[i][2] = fmaf(a.x, w0.z, fmaf(a.y, w1.z, fmaf(a.z, w2.z, fmaf(a.w, w3.z, acc[i][2]))));
            acc[i][3] = fmaf(a.x, w0.w, fmaf(a.y, w1.w, fmaf(a.z, w2.w, fmaf(a.w, w3.w, acc[i][3]))));
        }
    }
    __syncthreads();

    float4 bb = *(const float4*)(fb2 + cx);
#pragma unroll
    for (int i = 0; i < 4; i++) {
        Xs[(ry + i) * 64 + cx + 0] = acc[i][0] + bb.x;
        Xs[(ry + i) * 64 + cx + 1] = acc[i][1] + bb.y;
        Xs[(ry + i) * 64 + cx + 2] = acc[i][2] + bb.z;
        Xs[(ry + i) * 64 + cx + 3] = acc[i][3] + bb.w;
    }
#pragma unroll
    for (int t = 0; t < 8; t++) Ws[tid + t * 256] = ow[tid + t * 256];  // 64x32
    if (tid < 128) Ws[2048 + tid] = cw[tid];                             // 64x2
    __syncthreads();

    int c = tid & 31;
    int rb = (tid >> 5) * 8;
    for (int rr = 0; rr < 8; rr++) {
        int r = rb + rr;
        float a = __ldg(ob + c);
#pragma unroll 16
        for (int k = 0; k < 64; k++) a += Xs[r * 64 + k] * Ws[k * 32 + c];
        if (row0 + r < Nn) outF[(size_t)(row0 + r) * 32 + c] = a;
    }
    if (tid < 128) {
        int r = tid >> 1, cc = tid & 1;
        float a = __ldg(cb + cc);
#pragma unroll 16
        for (int k = 0; k < 64; k++) a += Xs[r * 64 + k] * Ws[2048 + k * 2 + cc];
        if (row0 + r < Nn) outT[(size_t)(row0 + r) * 2 + cc] = a;
    }
}

// ---------------------------------------------------------------------------
extern "C" void kernel_launch(void* const* d_in, const int* in_sizes, int n_in,
                              void* d_out, int out_size) {
    const float* xin[2] = {(const float*)d_in[0], (const float*)d_in[1]};
    const int* ei[2]    = {(const int*)d_in[2], (const int*)d_in[3]};
    const float* ew1[2] = {(const float*)d_in[4],  (const float*)d_in[10]};
    const float* eb1[2] = {(const float*)d_in[5],  (const float*)d_in[11]};
    const float* ew2[2] = {(const float*)d_in[6],  (const float*)d_in[12]};
    const float* eb2[2] = {(const float*)d_in[7],  (const float*)d_in[13]};
    const float* cw[2]  = {(const float*)d_in[8],  (const float*)d_in[14]};
    const float* cb[2]  = {(const float*)d_in[9],  (const float*)d_in[15]};
    const float* fw1 = (const float*)d_in[16];
    const float* fb1 = (const float*)d_in[17];
    const float* fw2 = (const float*)d_in[18];
    const float* fb2 = (const float*)d_in[19];
    const float* ow  = (const float*)d_in[20];
    const float* obv = (const float*)d_in[21];
    const float* clw = (const float*)d_in[22];
    const float* clb = (const float*)d_in[23];

    float *Yb, *Xb, *Fb, *Ab, *Db, *Wp, *bp;
    cudaGetSymbolAddress((void**)&Yb, g_Yb);
    cudaGetSymbolAddress((void**)&Xb, g_Xb);
    cudaGetSymbolAddress((void**)&Fb, g_Fb);
    cudaGetSymbolAddress((void**)&Ab, g_Ab);
    cudaGetSymbolAddress((void**)&Db, g_D);
    cudaGetSymbolAddress((void**)&Wp, g_Wp);
    cudaGetSymbolAddress((void**)&bp, g_bp);
    float* Y[2] = {Yb, Yb + (size_t)Nn * 64};
    float* X[2] = {Xb, Xb + (size_t)Nn * 64};
    float* A[2][3];
    for (int g = 0; g < 2; g++)
        for (int l = 0; l < 3; l++) A[g][l] = Ab + (size_t)(g * 3 + l) * Nn * 64;
    float* D[2] = {Db, Db + Nn};

    // Events for fork/join inside graph capture (created once; timing disabled).
    static cudaEvent_t evFork = nullptr, evJoin = nullptr;
    if (!evFork) {
        cudaEventCreateWithFlags(&evFork, cudaEventDisableTiming);
        cudaEventCreateWithFlags(&evJoin, cudaEventDisableTiming);
    }
    cudaStream_t s0 = 0;                    // capture-origin (legacy) stream
    cudaStream_t s1 = cudaStreamPerThread;  // built-in second stream

    const int SG = (Ee * 16) / 256;

    // ---- shared prologue (s0) ----
    cudaMemsetAsync(Db, 0, 2 * Nn * sizeof(float), s0);
    deg_count_k<<<(Ee + 255) / 256, 256, 0, s0>>>(ei[0], ei[1], D[0], D[1]);
    dinv_k<<<(Nn + 255) / 256, 256, 0, s0>>>(D[0], D[1]);
    prep_k<<<2, 256, 0, s0>>>(ew2[0], eb2[0], cw[0], ew2[1], eb2[1], cw[1], Wp, bp);
    cudaMemsetAsync(A[0][0], 0, 3 * NB, s0);   // chain-0 agg buffers

    // ---- chain 0, stage 1 (s0), then fork chain 1 one stage behind ----
    gemm128_k<<<GB2, 512, 0, s0>>>(xin[0], ew1[0], nullptr, eb1[0],
                                   Wp, bp, D[0], Y[0], 2, 0);
    cudaEventRecord(evFork, s0);
    cudaStreamWaitEvent(s1, evFork, 0);

    // ---- chain 1 on s1 (staggered by one stage) ----
    cudaMemsetAsync(A[1][0], 0, 3 * NB, s1);   // chain-1 agg buffers
    gemm128_k<<<GB2, 512, 0, s1>>>(xin[1], ew1[1], nullptr, eb1[1],
                                   Wp + 4096, bp + 64, D[1], Y[1], 2, 0);
    scatter_k<<<SG, 256, 0, s1>>>(Y[1], ei[1], A[1][0]);
    gemm128_k<<<GB2, 512, 0, s1>>>(Y[1], A[1][0], D[1], cb[1],
                                   cw[1] + 4096, nullptr, D[1], X[1], 1, 0);
    scatter_k<<<SG, 256, 0, s1>>>(X[1], ei[1], A[1][1]);
    gemm128_k<<<GB2, 512, 0, s1>>>(X[1], A[1][1], D[1], cb[1] + 64,
                                   cw[1] + 8192, nullptr, D[1], Y[1], 1, 0);
    scatter_k<<<SG, 256, 0, s1>>>(Y[1], ei[1], A[1][2]);
    cudaEventRecord(evJoin, s1);

    // ---- chain 0 continues on s0 ----
    scatter_k<<<SG, 256, 0, s0>>>(Y[0], ei[0], A[0][0]);
    gemm128_k<<<GB2, 512, 0, s0>>>(Y[0], A[0][0], D[0], cb[0],
                                   cw[0] + 4096, nullptr, D[0], X[0], 1, 0);
    scatter_k<<<SG, 256, 0, s0>>>(X[0], ei[0], A[0][1]);
    gemm128_k<<<GB2, 512, 0, s0>>>(X[0], A[0][1], D[0], cb[0] + 64,
                                   cw[0] + 8192, nullptr, D[0], Y[0], 1, 0);
    scatter_k<<<SG, 256, 0, s0>>>(Y[0], ei[0], A[0][2]);

    // Fusion layer 1 part a (chain-0 data) -> F
    gemm128_k<<<GB2, 512, 0, s0>>>(Y[0], A[0][2], D[0], cb[0] + 128,
                                   fw1, fb1, nullptr, Fb, 1, 0);

    // ---- join: chain-1 results needed for accumulating pass ----
    cudaStreamWaitEvent(s0, evJoin, 0);
    gemm128_k<<<GB2, 512, 0, s0>>>(Y[1], A[1][2], D[1], cb[1] + 128,
                                   fw1 + 4096, nullptr, nullptr, Fb, 1, 1);

    // Fusion layer 2 + both output heads
    head_k<<<(Nn + 63) / 64, 256, 0, s0>>>(Fb, fw2, fb2, ow, obv, clw, clb,
                                           (float*)d_out, (float*)d_out + (size_t)Nn * 32);
}

// round 6
// speedup vs baseline: 1.6327x; 1.4141x over previous
#include <cuda_runtime.h>

#define Nn 100000
#define Ee 1000000
#define GB2 ((Nn + 127) / 128)     /* 782 gemm blocks */
#define SCB 196                    /* scan blocks: ceil(Nn/512) */

// Scratch (device globals — no runtime allocation allowed)
__device__ float g_Yb[2][(size_t)Nn * 64];
__device__ float g_Xb[2][(size_t)Nn * 64];
__device__ float g_Fb[(size_t)Nn * 64];
__device__ float g_Ab[2][(size_t)Nn * 64];  // one agg buffer per graph (reused across layers)
__device__ float g_D[2][Nn];
__device__ float g_Wp[2][64 * 64];          // w2 @ W0
__device__ float g_bp[2][64];               // b2 @ W0
// CSR scratch
__device__ int g_cnt[2][Nn];
__device__ int g_rp[2][Nn + 1];
__device__ int g_wp[2][Nn];
__device__ int g_col[2][Ee];
__device__ int g_bs[2][256];

// ---------------------------------------------------------------------------
// CSR build: histogram -> exclusive scan -> placement fill
// ---------------------------------------------------------------------------
__global__ void hist_k(const int* __restrict__ e0, const int* __restrict__ e1,
                       int* __restrict__ c) {
    int e = blockIdx.x * blockDim.x + threadIdx.x;
    if (e < Ee) {
        atomicAdd(c + __ldg(e0 + Ee + e), 1);
        atomicAdd(c + Nn + __ldg(e1 + Ee + e), 1);
    }
}

__global__ void scan1_k(const int* __restrict__ cnt, int* __restrict__ rp,
                        int* __restrict__ bs) {
    int g = blockIdx.y;
    __shared__ int sh[512];
    int idx = blockIdx.x * 512 + threadIdx.x;
    int v = (idx < Nn) ? cnt[g * Nn + idx] : 0;
    sh[threadIdx.x] = v;
    __syncthreads();
#pragma unroll
    for (int o = 1; o < 512; o <<= 1) {
        int t = (threadIdx.x >= o) ? sh[threadIdx.x - o] : 0;
        __syncthreads();
        sh[threadIdx.x] += t;
        __syncthreads();
    }
    if (idx < Nn) rp[g * (Nn + 1) + idx] = sh[threadIdx.x];
    if (threadIdx.x == 511) bs[g * 256 + blockIdx.x] = sh[511];
}

__global__ void scan2_k(int* __restrict__ bs) {
    int g = blockIdx.x;
    __shared__ int sh[256];
    int v = (threadIdx.x < SCB) ? bs[g * 256 + threadIdx.x] : 0;
    sh[threadIdx.x] = v;
    __syncthreads();
#pragma unroll
    for (int o = 1; o < 256; o <<= 1) {
        int t = (threadIdx.x >= o) ? sh[threadIdx.x - o] : 0;
        __syncthreads();
        sh[threadIdx.x] += t;
        __syncthreads();
    }
    bs[g * 256 + threadIdx.x] = sh[threadIdx.x] - v;  // exclusive
}

__global__ void scan3_k(const int* __restrict__ cnt, int* __restrict__ rp,
                        const int* __restrict__ bs, int* __restrict__ wp) {
    int g = blockIdx.y;
    int idx = blockIdx.x * 512 + threadIdx.x;
    if (idx < Nn) {
        int ex = rp[g * (Nn + 1) + idx] - cnt[g * Nn + idx] + bs[g * 256 + blockIdx.x];
        rp[g * (Nn + 1) + idx] = ex;
        wp[g * Nn + idx] = ex;
    }
    if (idx == 0) rp[g * (Nn + 1) + Nn] = Ee;
}

__global__ void fill_k(const int* __restrict__ e0, const int* __restrict__ e1,
                       int* __restrict__ wp, int* __restrict__ col) {
    int e = blockIdx.x * blockDim.x + threadIdx.x;
    if (e >= Ee) return;
    {
        int dst = __ldg(e0 + Ee + e);
        int pos = atomicAdd(wp + dst, 1);
        col[pos] = __ldg(e0 + e);
    }
    {
        int dst = __ldg(e1 + Ee + e);
        int pos = atomicAdd(wp + Nn + dst, 1);
        col[Ee + pos] = __ldg(e1 + e);
    }
}

__global__ void dinv2_k(const int* __restrict__ rp, float* __restrict__ d) {
    int g = blockIdx.y;
    int i = blockIdx.x * blockDim.x + threadIdx.x;
    if (i < Nn) {
        int deg = rp[g * (Nn + 1) + i + 1] - rp[g * (Nn + 1) + i];
        d[g * Nn + i] = rsqrtf((float)deg + 1.f);
    }
}

// ---------------------------------------------------------------------------
// CSR aggregation (pure gather, no atomics): out[n,:] = sum_{e in adj(n)} y[col[e],:]
// 16 lanes per node, float4 per lane, 2-way unrolled for MLP.
// ---------------------------------------------------------------------------
__global__ __launch_bounds__(256) void agg_k(const float* __restrict__ y,
                                             const int* __restrict__ rp,
                                             const int* __restrict__ col,
                                             float* __restrict__ out) {
    int node = blockIdx.x * 16 + (threadIdx.x >> 4);
    if (node >= Nn) return;
    int j = (threadIdx.x & 15) * 4;
    int b = __ldg(rp + node), e = __ldg(rp + node + 1);
    float4 s0 = make_float4(0.f, 0.f, 0.f, 0.f);
    float4 s1 = make_float4(0.f, 0.f, 0.f, 0.f);
    int i = b;
    for (; i + 2 <= e; i += 2) {
        int a0 = __ldg(col + i), a1 = __ldg(col + i + 1);
        float4 v0 = *(const float4*)(y + (size_t)a0 * 64 + j);
        float4 v1 = *(const float4*)(y + (size_t)a1 * 64 + j);
        s0.x += v0.x; s0.y += v0.y; s0.z += v0.z; s0.w += v0.w;
        s1.x += v1.x; s1.y += v1.y; s1.z += v1.z; s1.w += v1.w;
    }
    if (i < e) {
        int a0 = __ldg(col + i);
        float4 v0 = *(const float4*)(y + (size_t)a0 * 64 + j);
        s0.x += v0.x; s0.y += v0.y; s0.z += v0.z; s0.w += v0.w;
    }
    s0.x += s1.x; s0.y += s1.y; s0.z += s1.z; s0.w += s1.w;
    *(float4*)(out + (size_t)node * 64 + j) = s0;
}

// ---------------------------------------------------------------------------
// Tiny precompute: Wp[g] = w2 @ cw[0];  bp[g] = b2 @ cw[0]
// ---------------------------------------------------------------------------
__global__ void prep_k(const float* __restrict__ w2a, const float* __restrict__ b2a,
                       const float* __restrict__ cwa,
                       const float* __restrict__ w2b, const float* __restrict__ b2b,
                       const float* __restrict__ cwb,
                       float* __restrict__ wp, float* __restrict__ bp) {
    int g = blockIdx.x;
    const float* w2 = g ? w2b : w2a;
    const float* b2 = g ? b2b : b2a;
    const float* cw = g ? cwb : cwa;
    __shared__ float A[4096], B[4096];
    int tid = threadIdx.x;
#pragma unroll
    for (int t = 0; t < 16; t++) {
        A[tid + t * 256] = w2[tid + t * 256];
        B[tid + t * 256] = cw[tid + t * 256];
    }
    __syncthreads();
    float* WP = wp + g * 4096;
#pragma unroll
    for (int t = 0; t < 16; t++) {
        int idx = tid + t * 256;
        int i = idx >> 6, j = idx & 63;
        float s = 0.f;
#pragma unroll 16
        for (int k = 0; k < 64; k++) s = fmaf(A[i * 64 + k], B[k * 64 + j], s);
        WP[idx] = s;
    }
    if (tid < 64) {
        float s = 0.f;
        for (int k = 0; k < 64; k++) s = fmaf(b2[k], B[k * 64 + tid], s);
        bp[g * 64 + tid] = s;
    }
}

// ---------------------------------------------------------------------------
// 128x64 GEMM tile, 512 threads, 4x4 register blocking, all-float4 LDS.
// Modes: 0 raw; 1 fused GCN epilogue; 2 fused encoder hidden.
// ---------------------------------------------------------------------------
__global__ __launch_bounds__(512, 2) void gemm128_k(
    const float* __restrict__ inA, const float* __restrict__ inAgg,
    const float* __restrict__ inDinv, const float* __restrict__ inBias,
    const float* __restrict__ W, const float* __restrict__ outBias,
    const float* __restrict__ outDinv, float* __restrict__ out,
    int mode, int accum) {
    __shared__ float Xs[128 * 64];
    __shared__ float Ws[64 * 64];
    __shared__ float W1s[256];
    __shared__ float B1s[64];

    int tid = threadIdx.x;
    int row0 = blockIdx.x * 128;

    const float4* W4 = (const float4*)W;
    ((float4*)Ws)[tid]       = __ldg(W4 + tid);
    ((float4*)Ws)[tid + 512] = __ldg(W4 + tid + 512);

    if (mode == 2) {
        if (tid < 256) W1s[tid] = __ldg(inAgg + tid);
        if (tid < 64)  B1s[tid] = __ldg(inBias + tid);
        __syncthreads();
    }

#pragma unroll
    for (int t = 0; t < 4; t++) {
        int lin = tid + t * 512;
        int r = lin >> 4;
        float4 v = make_float4(0.f, 0.f, 0.f, 0.f);
        if (row0 + r < Nn) {
            if (mode == 0) {
                v = ((const float4*)inA)[(size_t)(row0 + r) * 16 + (lin & 15)];
            } else if (mode == 1) {
                size_t idx = (size_t)(row0 + r) * 16 + (lin & 15);
                float4 a = ((const float4*)inA)[idx];
                float4 g = ((const float4*)inAgg)[idx];
                float dv = inDinv[row0 + r];
                float4 b = __ldg((const float4*)inBias + (lin & 15));
                v.x = fmaxf(fmaf(dv, g.x + a.x, b.x), 0.f);
                v.y = fmaxf(fmaf(dv, g.y + a.y, b.y), 0.f);
                v.z = fmaxf(fmaf(dv, g.z + a.z, b.z), 0.f);
                v.w = fmaxf(fmaf(dv, g.w + a.w, b.w), 0.f);
            } else {
                float4 xv = __ldg((const float4*)inA + (row0 + r));
                int c = (lin & 15) * 4;
                v.x = fmaxf(B1s[c+0] + xv.x*W1s[c+0] + xv.y*W1s[64+c+0] + xv.z*W1s[128+c+0] + xv.w*W1s[192+c+0], 0.f);
                v.y = fmaxf(B1s[c+1] + xv.x*W1s[c+1] + xv.y*W1s[64+c+1] + xv.z*W1s[128+c+1] + xv.w*W1s[192+c+1], 0.f);
                v.z = fmaxf(B1s[c+2] + xv.x*W1s[c+2] + xv.y*W1s[64+c+2] + xv.z*W1s[128+c+2] + xv.w*W1s[192+c+2], 0.f);
                v.w = fmaxf(B1s[c+3] + xv.x*W1s[c+3] + xv.y*W1s[64+c+3] + xv.z*W1s[128+c+3] + xv.w*W1s[192+c+3], 0.f);
            }
        }
        ((float4*)Xs)[lin] = v;
    }
    __syncthreads();

    int cx = (tid & 15) * 4;
    int ry = (tid >> 4) * 4;
    float acc[4][4];
#pragma unroll
    for (int i = 0; i < 4; i++)
#pragma unroll
        for (int j = 0; j < 4; j++) acc[i][j] = 0.f;

#pragma unroll
    for (int k0 = 0; k0 < 64; k0 += 4) {
        float4 w0 = *(const float4*)(Ws + (k0 + 0) * 64 + cx);
        float4 w1 = *(const float4*)(Ws + (k0 + 1) * 64 + cx);
        float4 w2 = *(const float4*)(Ws + (k0 + 2) * 64 + cx);
        float4 w3 = *(const float4*)(Ws + (k0 + 3) * 64 + cx);
#pragma unroll
        for (int i = 0; i < 4; i++) {
            float4 a = *(const float4*)(Xs + (ry + i) * 64 + k0);
            acc[i][0] = fmaf(a.x, w0.x, fmaf(a.y, w1.x, fmaf(a.z, w2.x, fmaf(a.w, w3.x, acc[i][0]))));
            acc[i][1] = fmaf(a.x, w0.y, fmaf(a.y, w1.y, fmaf(a.z, w2.y, fmaf(a.w, w3.y, acc[i][1]))));
            acc[i][2] = fmaf(a.x, w0.z, fmaf(a.y, w1.z, fmaf(a.z, w2.z, fmaf(a.w, w3.z, acc[i][2]))));
            acc[i][3] = fmaf(a.x, w0.w, fmaf(a.y, w1.w, fmaf(a.z, w2.w, fmaf(a.w, w3.w, acc[i][3]))));
        }
    }

    float4 obv = outBias ? __ldg((const float4*)(outBias + cx))
                         : make_float4(0.f, 0.f, 0.f, 0.f);
#pragma unroll
    for (int i = 0; i < 4; i++) {
        int r = row0 + ry + i;
        if (r < Nn) {
            float sc = outDinv ? outDinv[r] : 1.f;
            float4 o = make_float4((acc[i][0] + obv.x) * sc, (acc[i][1] + obv.y) * sc,
                                   (acc[i][2] + obv.z) * sc, (acc[i][3] + obv.w) * sc);
            float* p = out + (size_t)r * 64 + cx;
            if (accum) {
                float4 pv = *(const float4*)p;
                o.x += pv.x; o.y += pv.y; o.z += pv.z; o.w += pv.w;
            }
            *(float4*)p = o;
        }
    }
}

// ---------------------------------------------------------------------------
// Head: fused = relu(h1) @ fw2 + fb2; feats = fused@ow+ob; types = fused@cw+cb
// ---------------------------------------------------------------------------
__global__ __launch_bounds__(256) void head_k(
    const float* __restrict__ h1, const float* __restrict__ fw2, const float* __restrict__ fb2,
    const float* __restrict__ ow, const float* __restrict__ ob,
    const float* __restrict__ cw, const float* __restrict__ cb,
    float* __restrict__ outF, float* __restrict__ outT) {
    __shared__ float Xs[64 * 64];
    __shared__ float Ws[64 * 64];
    int tid = threadIdx.x;
    int row0 = blockIdx.x * 64;
    size_t base = (size_t)row0 * 64;

#pragma unroll
    for (int t = 0; t < 16; t++) Ws[tid + t * 256] = fw2[tid + t * 256];
#pragma unroll
    for (int t = 0; t < 16; t++) {
        int lin = tid + t * 256;
        int r = lin >> 6;
        Xs[lin] = (row0 + r < Nn) ? fmaxf(h1[base + lin], 0.f) : 0.f;
    }
    __syncthreads();

    int cx = (tid & 15) * 4;
    int ry = (tid >> 4) * 4;
    float acc[4][4];
#pragma unroll
    for (int i = 0; i < 4; i++)
#pragma unroll
        for (int j = 0; j < 4; j++) acc[i][j] = 0.f;

#pragma unroll
    for (int k0 = 0; k0 < 64; k0 += 4) {
        float4 w0 = *(const float4*)(Ws + (k0 + 0) * 64 + cx);
        float4 w1 = *(const float4*)(Ws + (k0 + 1) * 64 + cx);
        float4 w2 = *(const float4*)(Ws + (k0 + 2) * 64 + cx);
        float4 w3 = *(const float4*)(Ws + (k0 + 3) * 64 + cx);
#pragma unroll
        for (int i = 0; i < 4; i++) {
            float4 a = *(const float4*)(Xs + (ry + i) * 64 + k0);
            acc[i][0] = fmaf(a.x, w0.x, fmaf(a.y, w1.x, fmaf(a.z, w2.x, fmaf(a.w, w3.x, acc[i][0]))));
            acc[i][1] = fmaf(a.x, w0.y, fmaf(a.y, w1.y, fmaf(a.z, w2.y, fmaf(a.w, w3.y, acc[i][1]))));
            acc[i][2] = fmaf(a.x, w0.z, fmaf(a.y, w1.z, fmaf(a.z, w2.z, fmaf(a.w, w3.z, acc[i][2]))));
            acc[i][3] = fmaf(a.x, w0.w, fmaf(a.y, w1.w, fmaf(a.z, w2.w, fmaf(a.w, w3.w, acc[i][3]))));
        }
    }
    __syncthreads();

    float4 bb = *(const float4*)(fb2 + cx);
#pragma unroll
    for (int i = 0; i < 4; i++) {
        Xs[(ry + i) * 64 + cx + 0] = acc[i][0] + bb.x;
        Xs[(ry + i) * 64 + cx + 1] = acc[i][1] + bb.y;
        Xs[(ry + i) * 64 + cx + 2] = acc[i][2] + bb.z;
        Xs[(ry + i) * 64 + cx + 3] = acc[i][3] + bb.w;
    }
#pragma unroll
    for (int t = 0; t < 8; t++) Ws[tid + t * 256] = ow[tid + t * 256];  // 64x32
    if (tid < 128) Ws[2048 + tid] = cw[tid];                             // 64x2
    __syncthreads();

    int c = tid & 31;
    int rb = (tid >> 5) * 8;
    for (int rr = 0; rr < 8; rr++) {
        int r = rb + rr;
        float a = __ldg(ob + c);
#pragma unroll 16
        for (int k = 0; k < 64; k++) a += Xs[r * 64 + k] * Ws[k * 32 + c];
        if (row0 + r < Nn) outF[(size_t)(row0 + r) * 32 + c] = a;
    }
    if (tid < 128) {
        int r = tid >> 1, cc = tid & 1;
        float a = __ldg(cb + cc);
#pragma unroll 16
        for (int k = 0; k < 64; k++) a += Xs[r * 64 + k] * Ws[2048 + k * 2 + cc];
        if (row0 + r < Nn) outT[(size_t)(row0 + r) * 2 + cc] = a;
    }
}

// ---------------------------------------------------------------------------
extern "C" void kernel_launch(void* const* d_in, const int* in_sizes, int n_in,
                              void* d_out, int out_size) {
    const float* xin[2] = {(const float*)d_in[0], (const float*)d_in[1]};
    const int* ei[2]    = {(const int*)d_in[2], (const int*)d_in[3]};
    const float* ew1[2] = {(const float*)d_in[4],  (const float*)d_in[10]};
    const float* eb1[2] = {(const float*)d_in[5],  (const float*)d_in[11]};
    const float* ew2[2] = {(const float*)d_in[6],  (const float*)d_in[12]};
    const float* eb2[2] = {(const float*)d_in[7],  (const float*)d_in[13]};
    const float* cw[2]  = {(const float*)d_in[8],  (const float*)d_in[14]};
    const float* cb[2]  = {(const float*)d_in[9],  (const float*)d_in[15]};
    const float* fw1 = (const float*)d_in[16];
    const float* fb1 = (const float*)d_in[17];
    const float* fw2 = (const float*)d_in[18];
    const float* fb2 = (const float*)d_in[19];
    const float* ow  = (const float*)d_in[20];
    const float* obv = (const float*)d_in[21];
    const float* clw = (const float*)d_in[22];
    const float* clb = (const float*)d_in[23];

    float *Yb, *Xb, *Fb, *Ab, *Db, *Wp, *bp;
    int *cnt, *rp, *wpp, *colp, *bs;
    cudaGetSymbolAddress((void**)&Yb, g_Yb);
    cudaGetSymbolAddress((void**)&Xb, g_Xb);
    cudaGetSymbolAddress((void**)&Fb, g_Fb);
    cudaGetSymbolAddress((void**)&Ab, g_Ab);
    cudaGetSymbolAddress((void**)&Db, g_D);
    cudaGetSymbolAddress((void**)&Wp, g_Wp);
    cudaGetSymbolAddress((void**)&bp, g_bp);
    cudaGetSymbolAddress((void**)&cnt, g_cnt);
    cudaGetSymbolAddress((void**)&rp, g_rp);
    cudaGetSymbolAddress((void**)&wpp, g_wp);
    cudaGetSymbolAddress((void**)&colp, g_col);
    cudaGetSymbolAddress((void**)&bs, g_bs);
    float* Y[2] = {Yb, Yb + (size_t)Nn * 64};
    float* X[2] = {Xb, Xb + (size_t)Nn * 64};
    float* A[2] = {Ab, Ab + (size_t)Nn * 64};
    float* D[2] = {Db, Db + Nn};
    int* RP[2]  = {rp, rp + (Nn + 1)};
    int* COL[2] = {colp, colp + Ee};

    // ---- CSR build (both graphs) ----
    cudaMemsetAsync(cnt, 0, 2 * Nn * sizeof(int));
    hist_k<<<(Ee + 255) / 256, 256>>>(ei[0], ei[1], cnt);
    scan1_k<<<dim3(SCB, 2), 512>>>(cnt, rp, bs);
    scan2_k<<<2, 256>>>(bs);
    scan3_k<<<dim3(SCB, 2), 512>>>(cnt, rp, bs, wpp);
    fill_k<<<(Ee + 255) / 256, 256>>>(ei[0], ei[1], wpp, colp);
    dinv2_k<<<dim3((Nn + 255) / 256, 2), 256>>>(rp, Db);
    prep_k<<<2, 256>>>(ew2[0], eb2[0], cw[0], ew2[1], eb2[1], cw[1], Wp, bp);

    const int AGB = (Nn + 15) / 16;   // agg blocks

    for (int g = 0; g < 2; g++) {
        // Fused front: Y = (relu(x@w1+b1) @ Wp + bp) * dinv   (mode 2)
        gemm128_k<<<GB2, 512>>>(xin[g], ew1[g], nullptr, eb1[g],
                                Wp + g * 4096, bp + g * 64, D[g], Y[g], 2, 0);
        agg_k<<<AGB, 256>>>(Y[g], RP[g], COL[g], A[g]);

        // GCN layer 1: relu-gcn(Y, A) @ cw[1] * dinv -> X
        gemm128_k<<<GB2, 512>>>(Y[g], A[g], D[g], cb[g],
                                cw[g] + 4096, nullptr, D[g], X[g], 1, 0);
        agg_k<<<AGB, 256>>>(X[g], RP[g], COL[g], A[g]);

        // GCN layer 2: relu-gcn(X, A) @ cw[2] * dinv -> Y
        gemm128_k<<<GB2, 512>>>(X[g], A[g], D[g], cb[g] + 64,
                                cw[g] + 8192, nullptr, D[g], Y[g], 1, 0);
        agg_k<<<AGB, 256>>>(Y[g], RP[g], COL[g], A[g]);
    }

    // Fusion layer 1 (K=128 via two accumulating K=64 passes) -> F
    gemm128_k<<<GB2, 512>>>(Y[0], A[0], D[0], cb[0] + 128, fw1, fb1, nullptr, Fb, 1, 0);
    gemm128_k<<<GB2, 512>>>(Y[1], A[1], D[1], cb[1] + 128, fw1 + 4096, nullptr, nullptr, Fb, 1, 1);

    // Fusion layer 2 + both output heads
    head_k<<<(Nn + 63) / 64, 256>>>(Fb, fw2, fb2, ow, obv, clw, clb,
                                    (float*)d_out, (float*)d_out + (size_t)Nn * 32);
}